// round 14
// baseline (speedup 1.0000x reference)
#include <cuda_runtime.h>
#include <cstdint>

#define NPTS 1000000
#define NC   128
#define NG   100000

// scratch: group sums + counts (zeroed each launch via memset nodes)
__device__ float4 g_sums[(size_t)NG * 32];   // 51.2 MB, [G][32] float4
__device__ float  g_counts[NG];

__device__ __forceinline__ void red_add_v4(float* addr, float4 v) {
    asm volatile("red.global.add.v4.f32 [%0], {%1, %2, %3, %4};"
                 :: "l"(addr), "f"(v.x), "f"(v.y), "f"(v.z), "f"(v.w)
                 : "memory");
}

// one warp per 8 points; lane l handles float4 chunk l of each point.
// Body split into two 4-point waves (load 4 -> RED 4) to cut live registers;
// REDs are fire-and-forget so chip-level MLP is preserved via higher occupancy.
__global__ __launch_bounds__(256)
void accum_kernel(const float4* __restrict__ feat,
                  const int* __restrict__ gid) {
    int warp = (int)((blockIdx.x * (size_t)blockDim.x + threadIdx.x) >> 5);
    int lane = threadIdx.x & 31;
    int p0 = warp * 8;
    if (p0 >= NPTS) return;

    int g[8];
#pragma unroll
    for (int j = 0; j < 8; j++) {
        int t = __ldg(&gid[p0 + j]);
        g[j] = (t < 0) ? 0 : (t >= NG ? NG - 1 : t);
    }

#pragma unroll
    for (int h = 0; h < 2; h++) {           // two independent 4-point waves
        float4 v[4];
#pragma unroll
        for (int j = 0; j < 4; j++)
            v[j] = __ldcs(&feat[(size_t)(p0 + h * 4 + j) * 32 + lane]);  // stream
#pragma unroll
        for (int j = 0; j < 4; j++) {
            float* base = reinterpret_cast<float*>(
                g_sums + (size_t)g[h * 4 + j] * 32 + lane);
            red_add_v4(base, v[j]);          // fire-and-forget
        }
    }
    if (lane == 0) {
#pragma unroll
        for (int j = 0; j < 8; j++) atomicAdd(&g_counts[g[j]], 1.0f);  // REDG
    }
}

// fused mean + gather: out[p] = sums[g] * 1/max(count[g],1)
// one warp per 8 points, processed as FOUR 2-point waves -> minimal live registers
__global__ __launch_bounds__(256)
void gather_kernel(const int* __restrict__ gid,
                   float4* __restrict__ out) {
    int warp = (int)((blockIdx.x * (size_t)blockDim.x + threadIdx.x) >> 5);
    int lane = threadIdx.x & 31;
    int p0 = warp * 8;
    if (p0 >= NPTS) return;

    int g[8];
#pragma unroll
    for (int j = 0; j < 8; j++) {
        int t = __ldg(&gid[p0 + j]);
        g[j] = (t < 0) ? 0 : (t >= NG ? NG - 1 : t);
    }

#pragma unroll
    for (int h = 0; h < 4; h++) {           // four independent 2-point waves
        float4 v0 = g_sums[(size_t)g[h * 2 + 0] * 32 + lane];   // L2-resident
        float4 v1 = g_sums[(size_t)g[h * 2 + 1] * 32 + lane];
        float r0 = __frcp_rn(fmaxf(g_counts[g[h * 2 + 0]], 1.0f));
        float r1 = __frcp_rn(fmaxf(g_counts[g[h * 2 + 1]], 1.0f));
        float4 a = make_float4(v0.x * r0, v0.y * r0, v0.z * r0, v0.w * r0);
        float4 b = make_float4(v1.x * r1, v1.y * r1, v1.z * r1, v1.w * r1);
        __stcs(&out[(size_t)(p0 + h * 2 + 0) * 32 + lane], a);  // streaming
        __stcs(&out[(size_t)(p0 + h * 2 + 1) * 32 + lane], b);
    }
}

extern "C" void kernel_launch(void* const* d_in, const int* in_sizes, int n_in,
                              void* d_out, int out_size) {
    // inputs: [0] ref_bxyz f32 [N,4] (unused), [1] ref_feat f32 [N,128],
    //         [2] group_ids int32 [N]
    const float4* feat = (const float4*)d_in[1];
    const int*    gid  = (const int*)d_in[2];
    float4*       out  = (float4*)d_out;

    // zero scratch via memset nodes (graph-capturable, no kernel launch)
    void* sums_ptr = nullptr;
    void* counts_ptr = nullptr;
    cudaGetSymbolAddress(&sums_ptr, g_sums);
    cudaGetSymbolAddress(&counts_ptr, g_counts);
    cudaMemsetAsync(sums_ptr, 0, (size_t)NG * NC * sizeof(float));
    cudaMemsetAsync(counts_ptr, 0, (size_t)NG * sizeof(float));

    // one warp per 8 points, 256-thread blocks
    const int T = 256;
    size_t warps = (NPTS + 7) / 8;
    size_t threads = warps * 32;
    unsigned blocks = (unsigned)((threads + T - 1) / T);
    accum_kernel<<<blocks, T>>>(feat, gid);
    gather_kernel<<<blocks, T>>>(gid, out);
}

// round 16
// speedup vs baseline: 1.0130x; 1.0130x over previous
#include <cuda_runtime.h>
#include <cstdint>

#define NPTS 1000000
#define NC   128
#define NG   100000

// scratch: group sums + counts (zeroed each launch via memset nodes)
__device__ float4 g_sums[(size_t)NG * 32];   // 51.2 MB, [G][32] float4
__device__ float  g_counts[NG];

__device__ __forceinline__ void red_add_v4(float* addr, float4 v) {
    asm volatile("red.global.add.v4.f32 [%0], {%1, %2, %3, %4};"
                 :: "l"(addr), "f"(v.x), "f"(v.y), "f"(v.z), "f"(v.w)
                 : "memory");
}

// one warp per 8 points; lane l handles float4 chunk l of each point.
// (R13 winner shape — LTS RED-path bound; wave-splitting measured neutral)
__global__ void accum_kernel(const float4* __restrict__ feat,
                             const int* __restrict__ gid) {
    int warp = (int)((blockIdx.x * (size_t)blockDim.x + threadIdx.x) >> 5);
    int lane = threadIdx.x & 31;
    int p0 = warp * 8;
    if (p0 >= NPTS) return;

    int g[8];
#pragma unroll
    for (int j = 0; j < 8; j++) {
        int t = __ldg(&gid[p0 + j]);
        g[j] = (t < 0) ? 0 : (t >= NG ? NG - 1 : t);
    }

    float4 v[8];
#pragma unroll
    for (int j = 0; j < 8; j++)
        v[j] = __ldcs(&feat[(size_t)(p0 + j) * 32 + lane]);  // streaming read

#pragma unroll
    for (int j = 0; j < 8; j++) {
        float* base = reinterpret_cast<float*>(g_sums + (size_t)g[j] * 32 + lane);
        red_add_v4(base, v[j]);
    }
    if (lane == 0) {
#pragma unroll
        for (int j = 0; j < 8; j++) atomicAdd(&g_counts[g[j]], 1.0f);  // REDG
    }
}

// fused mean + gather: out[p] = sums[g] * 1/max(count[g],1)
// one warp per 4 points, two 2-point waves -> minimal regs, max resident warps
__global__ __launch_bounds__(256)
void gather_kernel(const int* __restrict__ gid,
                   float4* __restrict__ out) {
    int warp = (int)((blockIdx.x * (size_t)blockDim.x + threadIdx.x) >> 5);
    int lane = threadIdx.x & 31;
    int p0 = warp * 4;
    if (p0 >= NPTS) return;

    int g[4];
#pragma unroll
    for (int j = 0; j < 4; j++) {
        int t = __ldg(&gid[p0 + j]);
        g[j] = (t < 0) ? 0 : (t >= NG ? NG - 1 : t);
    }

#pragma unroll
    for (int h = 0; h < 2; h++) {           // two independent 2-point waves
        float4 v0 = g_sums[(size_t)g[h * 2 + 0] * 32 + lane];   // L2-resident
        float4 v1 = g_sums[(size_t)g[h * 2 + 1] * 32 + lane];
        float r0 = __frcp_rn(fmaxf(g_counts[g[h * 2 + 0]], 1.0f));
        float r1 = __frcp_rn(fmaxf(g_counts[g[h * 2 + 1]], 1.0f));
        float4 a = make_float4(v0.x * r0, v0.y * r0, v0.z * r0, v0.w * r0);
        float4 b = make_float4(v1.x * r1, v1.y * r1, v1.z * r1, v1.w * r1);
        __stcs(&out[(size_t)(p0 + h * 2 + 0) * 32 + lane], a);  // streaming
        __stcs(&out[(size_t)(p0 + h * 2 + 1) * 32 + lane], b);
    }
}

extern "C" void kernel_launch(void* const* d_in, const int* in_sizes, int n_in,
                              void* d_out, int out_size) {
    // inputs: [0] ref_bxyz f32 [N,4] (unused), [1] ref_feat f32 [N,128],
    //         [2] group_ids int32 [N]
    const float4* feat = (const float4*)d_in[1];
    const int*    gid  = (const int*)d_in[2];
    float4*       out  = (float4*)d_out;

    // zero scratch via memset nodes (graph-capturable, no kernel launch)
    void* sums_ptr = nullptr;
    void* counts_ptr = nullptr;
    cudaGetSymbolAddress(&sums_ptr, g_sums);
    cudaGetSymbolAddress(&counts_ptr, g_counts);
    cudaMemsetAsync(sums_ptr, 0, (size_t)NG * NC * sizeof(float));
    cudaMemsetAsync(counts_ptr, 0, (size_t)NG * sizeof(float));

    const int T = 256;

    // accum: one warp per 8 points
    {
        size_t warps = (NPTS + 7) / 8;
        size_t threads = warps * 32;
        unsigned blocks = (unsigned)((threads + T - 1) / T);
        accum_kernel<<<blocks, T>>>(feat, gid);
    }

    // gather: one warp per 4 points
    {
        size_t warps = (NPTS + 3) / 4;
        size_t threads = warps * 32;
        unsigned blocks = (unsigned)((threads + T - 1) / T);
        gather_kernel<<<blocks, T>>>(gid, out);
    }
}